// round 13
// baseline (speedup 1.0000x reference)
#include <cuda_runtime.h>
#include <cstdint>

// out = log( sum_m sum_k D[m,k] * x^k * b^m ) + CO_0
//   x = a*a/4 >= 0, all terms positive, D[0,0]=1 so S >= 1 (single __logf, no exps).
// COMPILE-TIME pruning (unchanged, verified rel_err 3.9e-7):
//   drop terms with D[m,k]*XMAX^k*BMAX^m < THRESH, XMAX=6.25, THRESH=1e-5.
// Heavy math in PACKED f32x2 (SASS FFMA2/FMUL2, PTX-only on Blackwell).
// R13 shape: float2/thread = ONE packed lane, 8192 warps (13.8/SMSP) --
// the kernel is latency-bound (issue 23.6%, occ 35% at R12's 4096 warps),
// so double the warps at constant per-element packed-op count.

constexpr int MM = 8;
constexpr int KK = 17;

__host__ __device__ constexpr double coefd(int m, int k) {
    double c = 1.0;
    for (int j = 1; j <= k; ++j)
        c *= (3.5 + (double)j) /
             (((double)j - 0.5) * (2.0 * m + 4.0 + (double)j) * (double)j);
    return c;
}
__host__ __device__ constexpr double rcoefd(int m) {
    double r = 1.0;
    for (int j = 1; j <= m; ++j)
        r *= ((2.0 * j - 1.5) * (2.0 * j - 0.5)) /
             (4.0 * (2.0 * j + 3.0) * (2.0 * j + 4.0) * (double)j * (double)j);
    return r;
}
__host__ __device__ constexpr double powc(double b, int e) {
    double r = 1.0;
    for (int i = 0; i < e; ++i) r *= b;
    return r;
}

constexpr double XMAX = 6.25, BMAX = 0.95, THRESH = 1e-5;

__host__ __device__ constexpr bool keepT(int m, int k) {
    return coefd(m, k) * rcoefd(m) * powc(XMAX, k) * powc(BMAX, m) >= THRESH;
}
__host__ __device__ constexpr bool rowLive(int m) {
    for (int k = 0; k < KK; ++k)
        if (keepT(m, k)) return true;
    return false;
}
__host__ __device__ constexpr int maxK() {
    int mk = 1;
    for (int m = 0; m < MM; ++m)
        for (int k = 0; k < KK; ++k)
            if (keepT(m, k) && k > mk) mk = k;
    return mk;
}
constexpr int KLIM = maxK();

__host__ __device__ constexpr int maxLiveRow() {
    int r = 0;
    for (int m = 0; m < MM; ++m)
        if (rowLive(m)) r = m;
    return r;
}
constexpr int RTOP = maxLiveRow();

__host__ __device__ constexpr float toF(double v) {
    return (v < 1e-37 && v > -1e-37) ? 0.0f : (float)v;
}

#define CO0_F (-0.15195235f)

// ---- packed f32x2 primitives ----

__device__ __forceinline__ uint64_t pk2(float lo, float hi) {
    uint64_t r;
    asm("mov.b64 %0, {%1, %2};" : "=l"(r) : "f"(lo), "f"(hi));
    return r;
}
__device__ __forceinline__ void upk2(float& lo, float& hi, uint64_t v) {
    asm("mov.b64 {%0, %1}, %2;" : "=f"(lo), "=f"(hi) : "l"(v));
}
__device__ __forceinline__ uint64_t mul2(uint64_t a, uint64_t b) {
    uint64_t r;
    asm("mul.rn.f32x2 %0, %1, %2;" : "=l"(r) : "l"(a), "l"(b));
    return r;
}
__device__ __forceinline__ uint64_t fma2(uint64_t a, uint64_t b, uint64_t c) {
    uint64_t r;
    asm("fma.rn.f32x2 %0, %1, %2, %3;" : "=l"(r) : "l"(a), "l"(b), "l"(c));
    return r;
}

// ---- template-unrolled packed core (single lane) ----

template <int M>
struct InitStep2 {
    __device__ static __forceinline__ void run(uint64_t* acc) {
        if constexpr (rowLive(M)) {
            constexpr float rv = toF(rcoefd(M));
            acc[M] = pk2(rv, rv);
        }
        InitStep2<M + 1>::run(acc);
    }
};
template <> struct InitStep2<MM> {
    __device__ static __forceinline__ void run(uint64_t*) {}
};

template <int M, int K>
struct MStep2 {
    __device__ static __forceinline__ void run(uint64_t xk, uint64_t* acc) {
        if constexpr (keepT(M, K)) {
            constexpr float cv = toF(coefd(M, K) * rcoefd(M));
            acc[M] = fma2(xk, pk2(cv, cv), acc[M]);
        }
        MStep2<M + 1, K>::run(xk, acc);
    }
};
template <int K> struct MStep2<MM, K> {
    __device__ static __forceinline__ void run(uint64_t, uint64_t*) {}
};

// even/odd packed power ladder: cur = x^K, nxt = x^(K+1); step: nxt' = cur*x2
template <int K>
struct KStepEO2 {
    __device__ static __forceinline__ void run(uint64_t x2, uint64_t cur,
                                               uint64_t nxt, uint64_t* acc) {
        MStep2<0, K>::run(cur, acc);
        if constexpr (K + 1 <= KLIM)
            KStepEO2<K + 1>::run(x2, nxt, mul2(cur, x2), acc);
    }
};

// packed Horner in b over live rows (descending)
template <int M>
struct HornerB2 {
    __device__ static __forceinline__ void run(const uint64_t* acc, uint64_t b,
                                               uint64_t& S) {
        S = fma2(S, b, acc[M]);
        HornerB2<M - 1>::run(acc, b, S);
    }
};
template <> struct HornerB2<-1> {
    __device__ static __forceinline__ void run(const uint64_t*, uint64_t,
                                               uint64_t&) {}
};

__global__ void __launch_bounds__(128)
ipe_vec2_kernel(const float2* __restrict__ a, const float2* __restrict__ b,
                float2* __restrict__ out, int n2) {
    int i = blockIdx.x * blockDim.x + threadIdx.x;
    if (i >= n2) return;
    float2 av = a[i];
    float2 bv = b[i];

    float x0 = av.x * av.x * 0.25f;
    float x1 = av.y * av.y * 0.25f;

    uint64_t xP = pk2(x0, x1);
    uint64_t x2P = mul2(xP, xP);

    uint64_t acc[MM];
    InitStep2<0>::run(acc);
    KStepEO2<1>::run(x2P, xP, x2P, acc);

    uint64_t bP = pk2(bv.x, bv.y);
    uint64_t S = acc[RTOP];
    HornerB2<RTOP - 1>::run(acc, bP, S);

    float s0, s1;
    upk2(s0, s1, S);

    float2 o;
    o.x = __logf(s0) + CO0_F;
    o.y = __logf(s1) + CO0_F;
    out[i] = o;
}

// ---- scalar fallback for the (empty in practice) tail ----

template <int M>
struct InitStepS {
    __device__ static __forceinline__ void run(float* acc) {
        if constexpr (rowLive(M)) acc[M] = toF(rcoefd(M));
        InitStepS<M + 1>::run(acc);
    }
};
template <> struct InitStepS<MM> { __device__ static __forceinline__ void run(float*) {} };

template <int M, int K>
struct MStepS {
    __device__ static __forceinline__ void run(float xk, float* acc) {
        if constexpr (keepT(M, K))
            acc[M] = fmaf(xk, toF(coefd(M, K) * rcoefd(M)), acc[M]);
        MStepS<M + 1, K>::run(xk, acc);
    }
};
template <int K> struct MStepS<MM, K> { __device__ static __forceinline__ void run(float, float*) {} };

template <int K>
struct KStepS {
    __device__ static __forceinline__ void run(float x2, float cur, float nxt,
                                               float* acc) {
        MStepS<0, K>::run(cur, acc);
        if constexpr (K + 1 <= KLIM)
            KStepS<K + 1>::run(x2, nxt, cur * x2, acc);
    }
};

template <int M>
struct HornerS {
    __device__ static __forceinline__ void run(const float* acc, float b,
                                               float& S) {
        S = fmaf(S, b, acc[M]);
        HornerS<M - 1>::run(acc, b, S);
    }
};
template <> struct HornerS<-1> {
    __device__ static __forceinline__ void run(const float*, float, float&) {}
};

__global__ void __launch_bounds__(128)
ipe_tail_kernel(const float* __restrict__ a, const float* __restrict__ b,
                float* __restrict__ out, int start, int n) {
    int i = start + blockIdx.x * blockDim.x + threadIdx.x;
    if (i >= n) return;
    float x = a[i] * a[i] * 0.25f;
    float acc[MM];
    InitStepS<0>::run(acc);
    float x2 = x * x;
    KStepS<1>::run(x2, x, x2, acc);
    float S = acc[RTOP];
    HornerS<RTOP - 1>::run(acc, b[i], S);
    out[i] = __logf(S) + CO0_F;
}

extern "C" void kernel_launch(void* const* d_in, const int* in_sizes, int n_in,
                              void* d_out, int out_size) {
    const float* a = (const float*)d_in[0];
    const float* b = (const float*)d_in[1];
    float* out = (float*)d_out;
    int n = in_sizes[0];
    int n2 = n / 2;
    if (n2 > 0) {
        int threads = 128;
        int blocks = (n2 + threads - 1) / threads;
        ipe_vec2_kernel<<<blocks, threads>>>((const float2*)a, (const float2*)b,
                                             (float2*)out, n2);
    }
    int rem = n - n2 * 2;
    if (rem > 0) {
        ipe_tail_kernel<<<1, 128>>>(a, b, out, n2 * 2, n);
    }
}

// round 14
// speedup vs baseline: 1.0539x; 1.0539x over previous
#include <cuda_runtime.h>
#include <cstdint>

// out = log( sum_m sum_k D[m,k] * x^k * b^m ) + CO_0
//   x = a*a/4 >= 0, all terms positive, D[0,0]=1 so S >= 1 (single __logf).
// COMPILE-TIME pruning (verified rel_err 3.9e-7 across rounds):
//   drop terms with D[m,k]*XMAX^k*BMAX^m < THRESH, XMAX=6.25, THRESH=1e-5.
// Heavy math in PACKED f32x2 (SASS FFMA2/FMUL2, PTX-only on Blackwell).
// R14 shape: vec8/thread = 4 packed lanes, 4 front-batched LDG.128 (MLP=4),
// 2048 warps, 128-thread blocks. Targets exposed DRAM latency + per-element
// overhead; kernel is NOT issue/warp-bound (R12/R13 evidence).

constexpr int MM = 8;
constexpr int KK = 17;

__host__ __device__ constexpr double coefd(int m, int k) {
    double c = 1.0;
    for (int j = 1; j <= k; ++j)
        c *= (3.5 + (double)j) /
             (((double)j - 0.5) * (2.0 * m + 4.0 + (double)j) * (double)j);
    return c;
}
__host__ __device__ constexpr double rcoefd(int m) {
    double r = 1.0;
    for (int j = 1; j <= m; ++j)
        r *= ((2.0 * j - 1.5) * (2.0 * j - 0.5)) /
             (4.0 * (2.0 * j + 3.0) * (2.0 * j + 4.0) * (double)j * (double)j);
    return r;
}
__host__ __device__ constexpr double powc(double b, int e) {
    double r = 1.0;
    for (int i = 0; i < e; ++i) r *= b;
    return r;
}

constexpr double XMAX = 6.25, BMAX = 0.95, THRESH = 1e-5;

__host__ __device__ constexpr bool keepT(int m, int k) {
    return coefd(m, k) * rcoefd(m) * powc(XMAX, k) * powc(BMAX, m) >= THRESH;
}
__host__ __device__ constexpr bool rowLive(int m) {
    for (int k = 0; k < KK; ++k)
        if (keepT(m, k)) return true;
    return false;
}
__host__ __device__ constexpr int maxK() {
    int mk = 1;
    for (int m = 0; m < MM; ++m)
        for (int k = 0; k < KK; ++k)
            if (keepT(m, k) && k > mk) mk = k;
    return mk;
}
constexpr int KLIM = maxK();

__host__ __device__ constexpr int maxLiveRow() {
    int r = 0;
    for (int m = 0; m < MM; ++m)
        if (rowLive(m)) r = m;
    return r;
}
constexpr int RTOP = maxLiveRow();

__host__ __device__ constexpr float toF(double v) {
    return (v < 1e-37 && v > -1e-37) ? 0.0f : (float)v;
}

#define CO0_F (-0.15195235f)

// ---- packed f32x2 primitives ----

__device__ __forceinline__ uint64_t pk2(float lo, float hi) {
    uint64_t r;
    asm("mov.b64 %0, {%1, %2};" : "=l"(r) : "f"(lo), "f"(hi));
    return r;
}
__device__ __forceinline__ void upk2(float& lo, float& hi, uint64_t v) {
    asm("mov.b64 {%0, %1}, %2;" : "=f"(lo), "=f"(hi) : "l"(v));
}
__device__ __forceinline__ uint64_t mul2(uint64_t a, uint64_t b) {
    uint64_t r;
    asm("mul.rn.f32x2 %0, %1, %2;" : "=l"(r) : "l"(a), "l"(b));
    return r;
}
__device__ __forceinline__ uint64_t fma2(uint64_t a, uint64_t b, uint64_t c) {
    uint64_t r;
    asm("fma.rn.f32x2 %0, %1, %2, %3;" : "=l"(r) : "l"(a), "l"(b), "l"(c));
    return r;
}

// ---- template-unrolled packed core, 4 independent lanes ----

constexpr int NL = 4;  // packed lanes per thread (8 scalar elements)

template <int M>
struct InitStep2 {
    __device__ static __forceinline__ void run(uint64_t (*acc)[NL]) {
        if constexpr (rowLive(M)) {
            constexpr float rv = toF(rcoefd(M));
#pragma unroll
            for (int l = 0; l < NL; ++l) acc[M][l] = pk2(rv, rv);
        }
        InitStep2<M + 1>::run(acc);
    }
};
template <> struct InitStep2<MM> {
    __device__ static __forceinline__ void run(uint64_t (*)[NL]) {}
};

template <int M, int K>
struct MStep2 {
    __device__ static __forceinline__ void run(const uint64_t* xk,
                                               uint64_t (*acc)[NL]) {
        if constexpr (keepT(M, K)) {
            constexpr float cv = toF(coefd(M, K) * rcoefd(M));
            uint64_t cc = pk2(cv, cv);   // CSE'd across lanes by ptxas
#pragma unroll
            for (int l = 0; l < NL; ++l) acc[M][l] = fma2(xk[l], cc, acc[M][l]);
        }
        MStep2<M + 1, K>::run(xk, acc);
    }
};
template <int K> struct MStep2<MM, K> {
    __device__ static __forceinline__ void run(const uint64_t*,
                                               uint64_t (*)[NL]) {}
};

// even/odd packed power ladder per lane: cur = x^K, nxt = x^(K+1)
template <int K>
struct KStepEO2 {
    __device__ static __forceinline__ void run(const uint64_t* x2,
                                               const uint64_t* cur,
                                               const uint64_t* nxt,
                                               uint64_t (*acc)[NL]) {
        MStep2<0, K>::run(cur, acc);
        if constexpr (K + 1 <= KLIM) {
            uint64_t nn[NL];
#pragma unroll
            for (int l = 0; l < NL; ++l) nn[l] = mul2(cur[l], x2[l]);
            KStepEO2<K + 1>::run(x2, nxt, nn, acc);
        }
    }
};

// packed Horner in b over live rows (descending), per lane
template <int M>
struct HornerB2 {
    __device__ static __forceinline__ void run(const uint64_t (*acc)[NL],
                                               const uint64_t* b,
                                               uint64_t* S) {
#pragma unroll
        for (int l = 0; l < NL; ++l) S[l] = fma2(S[l], b[l], acc[M][l]);
        HornerB2<M - 1>::run(acc, b, S);
    }
};
template <> struct HornerB2<-1> {
    __device__ static __forceinline__ void run(const uint64_t (*)[NL],
                                               const uint64_t*, uint64_t*) {}
};

// Each thread handles float4 indices i and i+half (half in float4 units).
__global__ void __launch_bounds__(128)
ipe_vec8_kernel(const float4* __restrict__ a, const float4* __restrict__ b,
                float4* __restrict__ out, int half) {
    int i = blockIdx.x * blockDim.x + threadIdx.x;
    if (i >= half) return;

    // front-batched loads: MLP = 4 LDG.128
    float4 a0 = a[i];
    float4 a1 = a[i + half];
    float4 b0 = b[i];
    float4 b1 = b[i + half];

    uint64_t xP[NL], x2P[NL], bP[NL];
    xP[0] = pk2(a0.x * a0.x * 0.25f, a0.y * a0.y * 0.25f);
    xP[1] = pk2(a0.z * a0.z * 0.25f, a0.w * a0.w * 0.25f);
    xP[2] = pk2(a1.x * a1.x * 0.25f, a1.y * a1.y * 0.25f);
    xP[3] = pk2(a1.z * a1.z * 0.25f, a1.w * a1.w * 0.25f);
#pragma unroll
    for (int l = 0; l < NL; ++l) x2P[l] = mul2(xP[l], xP[l]);
    bP[0] = pk2(b0.x, b0.y);
    bP[1] = pk2(b0.z, b0.w);
    bP[2] = pk2(b1.x, b1.y);
    bP[3] = pk2(b1.z, b1.w);

    uint64_t acc[MM][NL];
    InitStep2<0>::run(acc);
    KStepEO2<1>::run(x2P, xP, x2P, acc);

    uint64_t S[NL];
#pragma unroll
    for (int l = 0; l < NL; ++l) S[l] = acc[RTOP][l];
    HornerB2<RTOP - 1>::run(acc, bP, S);

    float s[2 * NL];
#pragma unroll
    for (int l = 0; l < NL; ++l) upk2(s[2 * l], s[2 * l + 1], S[l]);

    float4 o0, o1;
    o0.x = __logf(s[0]) + CO0_F;
    o0.y = __logf(s[1]) + CO0_F;
    o0.z = __logf(s[2]) + CO0_F;
    o0.w = __logf(s[3]) + CO0_F;
    o1.x = __logf(s[4]) + CO0_F;
    o1.y = __logf(s[5]) + CO0_F;
    o1.z = __logf(s[6]) + CO0_F;
    o1.w = __logf(s[7]) + CO0_F;
    out[i] = o0;
    out[i + half] = o1;
}

// ---- scalar fallback for any tail elements ----

template <int M>
struct InitStepS {
    __device__ static __forceinline__ void run(float* acc) {
        if constexpr (rowLive(M)) acc[M] = toF(rcoefd(M));
        InitStepS<M + 1>::run(acc);
    }
};
template <> struct InitStepS<MM> { __device__ static __forceinline__ void run(float*) {} };

template <int M, int K>
struct MStepS {
    __device__ static __forceinline__ void run(float xk, float* acc) {
        if constexpr (keepT(M, K))
            acc[M] = fmaf(xk, toF(coefd(M, K) * rcoefd(M)), acc[M]);
        MStepS<M + 1, K>::run(xk, acc);
    }
};
template <int K> struct MStepS<MM, K> { __device__ static __forceinline__ void run(float, float*) {} };

template <int K>
struct KStepS {
    __device__ static __forceinline__ void run(float x2, float cur, float nxt,
                                               float* acc) {
        MStepS<0, K>::run(cur, acc);
        if constexpr (K + 1 <= KLIM)
            KStepS<K + 1>::run(x2, nxt, cur * x2, acc);
    }
};

template <int M>
struct HornerS {
    __device__ static __forceinline__ void run(const float* acc, float b,
                                               float& S) {
        S = fmaf(S, b, acc[M]);
        HornerS<M - 1>::run(acc, b, S);
    }
};
template <> struct HornerS<-1> {
    __device__ static __forceinline__ void run(const float*, float, float&) {}
};

__global__ void __launch_bounds__(128)
ipe_tail_kernel(const float* __restrict__ a, const float* __restrict__ b,
                float* __restrict__ out, int start, int n) {
    int i = start + blockIdx.x * blockDim.x + threadIdx.x;
    if (i >= n) return;
    float x = a[i] * a[i] * 0.25f;
    float acc[MM];
    InitStepS<0>::run(acc);
    float x2 = x * x;
    KStepS<1>::run(x2, x, x2, acc);
    float S = acc[RTOP];
    HornerS<RTOP - 1>::run(acc, b[i], S);
    out[i] = __logf(S) + CO0_F;
}

extern "C" void kernel_launch(void* const* d_in, const int* in_sizes, int n_in,
                              void* d_out, int out_size) {
    const float* a = (const float*)d_in[0];
    const float* b = (const float*)d_in[1];
    float* out = (float*)d_out;
    int n = in_sizes[0];
    int n8 = n / 8;           // vec8 groups
    int half = n8;            // float4 index offset between a thread's two loads
    if (n8 > 0) {
        int threads = 128;
        int blocks = (n8 + threads - 1) / threads;
        ipe_vec8_kernel<<<blocks, threads>>>((const float4*)a, (const float4*)b,
                                             (float4*)out, half);
    }
    int done = n8 * 8;
    if (n - done > 0) {
        int threads = 128;
        int blocks = (n - done + threads - 1) / threads;
        ipe_tail_kernel<<<blocks, threads>>>(a, b, out, done, n);
    }
}